// round 14
// baseline (speedup 1.0000x reference)
#include <cuda_runtime.h>
#include <stdint.h>

#define NN 100000
#define NE 1000000
#define D  64

// Scratch: scatter-sum accumulator [NN, D] (device global => allowed, no alloc).
// 256B-aligned: accessed via float4 and red.global.add.v4.f32 (trap if misaligned).
__device__ __align__(256) float g_agg[(size_t)NN * D];

// Runtime dtype flag for edge_index: 1 = int64, 0 = int32.
__device__ int g_idx_is64;

// ---------------------------------------------------------------------------
// Detect edge_index dtype. Reads first 64 int64 slots (512 bytes — in-bounds
// under either interpretation: buffer is >= 8 MB). True-int64 indices all lie
// in [0, NN); int32 data read as int64 fuses pairs (a + b*2^32), which exceeds
// NN unless the high half is 0 (P ~= 1e-5 per sample -> never all 64).
// ---------------------------------------------------------------------------
__global__ void detect_kernel(const long long* eidx64) {
    if (threadIdx.x == 0 && blockIdx.x == 0) {
        int all_ok = 1;
        for (int i = 0; i < 64; i++) {
            long long v = eidx64[i];
            if (v < 0 || v >= NN) { all_ok = 0; break; }
        }
        g_idx_is64 = all_ok;
    }
}

// ---------------------------------------------------------------------------
// Zero the aggregation buffer (kernel, not cudaMemset, to stay graph-safe)
// ---------------------------------------------------------------------------
__global__ void zero_agg_kernel() {
    size_t i = (size_t)blockIdx.x * blockDim.x + threadIdx.x;
    const size_t total = (size_t)NN * D / 4;
    if (i < total) {
        float4 z; z.x = 0.f; z.y = 0.f; z.z = 0.f; z.w = 0.f;
        reinterpret_cast<float4*>(g_agg)[i] = z;
    }
}

// ---------------------------------------------------------------------------
// Vector reduction into global memory (sm_90+): 1 instruction per 4 floats
// ---------------------------------------------------------------------------
__device__ __forceinline__ void red_add_v4(float* p, float a, float b, float c, float d) {
    asm volatile("red.global.add.v4.f32 [%0], {%1, %2, %3, %4};"
                 :: "l"(p), "f"(a), "f"(b), "f"(c), "f"(d) : "memory");
}

// ---------------------------------------------------------------------------
// Edge kernel: msg = relu(x[row] @ W1 + b1) @ W2 + b2; scatter-add to g_agg[col]
// ---------------------------------------------------------------------------
constexpr int TE = 128;   // edges per tile
constexpr int XS = 65;    // padded row stride (floats) -> conflict-free k reads

struct __align__(16) ESmem {
    float w1[D * D];
    float w2[D * D];
    float b1[D];
    float b2[D];
    float x[TE * XS];     // gathered x tile, later reused as H tile
    int   col[TE];
};

__global__ __launch_bounds__(128) void edge_kernel(
    const float* __restrict__ x,
    const void* __restrict__ eidx_raw,   // [2, NE], int32 OR int64 (see g_idx_is64)
    const float* __restrict__ w1, const float* __restrict__ b1,
    const float* __restrict__ w2, const float* __restrict__ b2)
{
    extern __shared__ char smem_raw[];
    ESmem& s = *reinterpret_cast<ESmem*>(smem_raw);
    const int tid = threadIdx.x;
    const int use64 = g_idx_is64;
    const int*       e32 = reinterpret_cast<const int*>(eidx_raw);
    const long long* e64 = reinterpret_cast<const long long*>(eidx_raw);

    // Load weights once per block
    for (int i = tid; i < D * D / 4; i += 128) {
        reinterpret_cast<float4*>(s.w1)[i] = reinterpret_cast<const float4*>(w1)[i];
        reinterpret_cast<float4*>(s.w2)[i] = reinterpret_cast<const float4*>(w2)[i];
    }
    if (tid < D) { s.b1[tid] = b1[tid]; s.b2[tid] = b2[tid]; }

    const int eg = tid >> 3;          // 0..15  (edge group: 8 edges)
    const int cg = tid & 7;           // 0..7   (col group: 8 cols)
    const int e0 = eg * 8;
    const int c0 = cg * 8;
    const int ntiles = (NE + TE - 1) / TE;

    for (int tile = blockIdx.x; tile < ntiles; tile += gridDim.x) {
        __syncthreads();   // weights ready (1st iter) / prev iter done with smem

        // ---- gather: one edge per thread ----
        const int e = tile * TE + tid;
        int r = 0, c = -1;
        if (e < NE) {
            if (use64) {
                r = (int)e64[e];
                c = (int)e64[NE + e];
            } else {
                r = e32[e];
                c = e32[NE + e];
            }
            // Safety clamp: converts any residual index-format surprise into a
            // finite rel_err instead of an illegal access (diagnostic, ~free).
            r = min(max(r, 0), NN - 1);
            c = min(c, NN - 1);
        }
        s.col[tid] = c;
        const float4* xr = reinterpret_cast<const float4*>(x + (size_t)r * D);
        #pragma unroll
        for (int j = 0; j < 16; j++) {
            float4 v = xr[j];
            float* dst = &s.x[tid * XS + 4 * j];
            dst[0] = v.x; dst[1] = v.y; dst[2] = v.z; dst[3] = v.w;
        }
        __syncthreads();

        // ---- layer 1: H = relu(X @ W1 + b1) ----
        float acc[8][8];
        #pragma unroll
        for (int i = 0; i < 8; i++)
            #pragma unroll
            for (int j = 0; j < 8; j++) acc[i][j] = s.b1[c0 + j];

        #pragma unroll 4
        for (int k = 0; k < D; k++) {
            float a[8], b[8];
            #pragma unroll
            for (int i = 0; i < 8; i++) a[i] = s.x[(e0 + i) * XS + k];
            float4 bv0 = *reinterpret_cast<const float4*>(&s.w1[k * D + c0]);
            float4 bv1 = *reinterpret_cast<const float4*>(&s.w1[k * D + c0 + 4]);
            b[0] = bv0.x; b[1] = bv0.y; b[2] = bv0.z; b[3] = bv0.w;
            b[4] = bv1.x; b[5] = bv1.y; b[6] = bv1.z; b[7] = bv1.w;
            #pragma unroll
            for (int i = 0; i < 8; i++)
                #pragma unroll
                for (int j = 0; j < 8; j++) acc[i][j] = fmaf(a[i], b[j], acc[i][j]);
        }
        __syncthreads();   // everyone done reading X before overwrite

        // relu + store H in place of X
        #pragma unroll
        for (int i = 0; i < 8; i++)
            #pragma unroll
            for (int j = 0; j < 8; j++)
                s.x[(e0 + i) * XS + c0 + j] = fmaxf(acc[i][j], 0.f);
        __syncthreads();

        // ---- layer 2: M = H @ W2 + b2 ----
        #pragma unroll
        for (int i = 0; i < 8; i++)
            #pragma unroll
            for (int j = 0; j < 8; j++) acc[i][j] = s.b2[c0 + j];

        #pragma unroll 4
        for (int k = 0; k < D; k++) {
            float a[8], b[8];
            #pragma unroll
            for (int i = 0; i < 8; i++) a[i] = s.x[(e0 + i) * XS + k];
            float4 bv0 = *reinterpret_cast<const float4*>(&s.w2[k * D + c0]);
            float4 bv1 = *reinterpret_cast<const float4*>(&s.w2[k * D + c0 + 4]);
            b[0] = bv0.x; b[1] = bv0.y; b[2] = bv0.z; b[3] = bv0.w;
            b[4] = bv1.x; b[5] = bv1.y; b[6] = bv1.z; b[7] = bv1.w;
            #pragma unroll
            for (int i = 0; i < 8; i++)
                #pragma unroll
                for (int j = 0; j < 8; j++) acc[i][j] = fmaf(a[i], b[j], acc[i][j]);
        }

        // ---- scatter-add into g_agg[col] ----
        #pragma unroll
        for (int i = 0; i < 8; i++) {
            int cc = s.col[e0 + i];
            if (cc >= 0) {
                float* dst = g_agg + (size_t)cc * D + c0;
                red_add_v4(dst,     acc[i][0], acc[i][1], acc[i][2], acc[i][3]);
                red_add_v4(dst + 4, acc[i][4], acc[i][5], acc[i][6], acc[i][7]);
            }
        }
    }
}

// ---------------------------------------------------------------------------
// Node kernel: out = relu([x, agg] @ Wo1 + bo1) @ Wo2 + bo2
// ---------------------------------------------------------------------------
constexpr int TN  = 128;   // nodes per tile
constexpr int NXS = 129;   // padded row stride for [x|agg] tile (128 + 1)

struct __align__(16) NSmem {
    float w1[2 * D * D];   // [128, 64]
    float w2[D * D];       // [64, 64]
    float b1[D];
    float b2[D];
    float xa[TN * NXS];    // concat tile, later reused as H tile
};

__global__ __launch_bounds__(128) void node_kernel(
    const float* __restrict__ x,
    const float* __restrict__ w1, const float* __restrict__ b1,
    const float* __restrict__ w2, const float* __restrict__ b2,
    float* __restrict__ out)
{
    extern __shared__ char smem_raw[];
    NSmem& s = *reinterpret_cast<NSmem*>(smem_raw);
    const int tid = threadIdx.x;

    for (int i = tid; i < 2 * D * D / 4; i += 128)
        reinterpret_cast<float4*>(s.w1)[i] = reinterpret_cast<const float4*>(w1)[i];
    for (int i = tid; i < D * D / 4; i += 128)
        reinterpret_cast<float4*>(s.w2)[i] = reinterpret_cast<const float4*>(w2)[i];
    if (tid < D) { s.b1[tid] = b1[tid]; s.b2[tid] = b2[tid]; }

    const int ng = tid >> 3;
    const int cg = tid & 7;
    const int n0 = ng * 8;
    const int c0 = cg * 8;
    const int ntiles = (NN + TN - 1) / TN;

    for (int tile = blockIdx.x; tile < ntiles; tile += gridDim.x) {
        __syncthreads();

        // ---- gather [x | agg] for 128 nodes (one node per thread) ----
        const int n = tile * TN + tid;
        const int src = (n < NN) ? n : 0;
        const float4* xr = reinterpret_cast<const float4*>(x + (size_t)src * D);
        const float4* ar = reinterpret_cast<const float4*>(g_agg + (size_t)src * D);
        #pragma unroll
        for (int j = 0; j < 16; j++) {
            float4 v = xr[j];
            float* dst = &s.xa[tid * NXS + 4 * j];
            dst[0] = v.x; dst[1] = v.y; dst[2] = v.z; dst[3] = v.w;
        }
        #pragma unroll
        for (int j = 0; j < 16; j++) {
            float4 v = ar[j];
            float* dst = &s.xa[tid * NXS + D + 4 * j];
            dst[0] = v.x; dst[1] = v.y; dst[2] = v.z; dst[3] = v.w;
        }
        __syncthreads();

        // ---- layer 1: K = 128 ----
        float acc[8][8];
        #pragma unroll
        for (int i = 0; i < 8; i++)
            #pragma unroll
            for (int j = 0; j < 8; j++) acc[i][j] = s.b1[c0 + j];

        #pragma unroll 4
        for (int k = 0; k < 2 * D; k++) {
            float a[8], b[8];
            #pragma unroll
            for (int i = 0; i < 8; i++) a[i] = s.xa[(n0 + i) * NXS + k];
            float4 bv0 = *reinterpret_cast<const float4*>(&s.w1[k * D + c0]);
            float4 bv1 = *reinterpret_cast<const float4*>(&s.w1[k * D + c0 + 4]);
            b[0] = bv0.x; b[1] = bv0.y; b[2] = bv0.z; b[3] = bv0.w;
            b[4] = bv1.x; b[5] = bv1.y; b[6] = bv1.z; b[7] = bv1.w;
            #pragma unroll
            for (int i = 0; i < 8; i++)
                #pragma unroll
                for (int j = 0; j < 8; j++) acc[i][j] = fmaf(a[i], b[j], acc[i][j]);
        }
        __syncthreads();

        #pragma unroll
        for (int i = 0; i < 8; i++)
            #pragma unroll
            for (int j = 0; j < 8; j++)
                s.xa[(n0 + i) * NXS + c0 + j] = fmaxf(acc[i][j], 0.f);
        __syncthreads();

        // ---- layer 2: K = 64 ----
        #pragma unroll
        for (int i = 0; i < 8; i++)
            #pragma unroll
            for (int j = 0; j < 8; j++) acc[i][j] = s.b2[c0 + j];

        #pragma unroll 4
        for (int k = 0; k < D; k++) {
            float a[8], b[8];
            #pragma unroll
            for (int i = 0; i < 8; i++) a[i] = s.xa[(n0 + i) * NXS + k];
            float4 bv0 = *reinterpret_cast<const float4*>(&s.w2[k * D + c0]);
            float4 bv1 = *reinterpret_cast<const float4*>(&s.w2[k * D + c0 + 4]);
            b[0] = bv0.x; b[1] = bv0.y; b[2] = bv0.z; b[3] = bv0.w;
            b[4] = bv1.x; b[5] = bv1.y; b[6] = bv1.z; b[7] = bv1.w;
            #pragma unroll
            for (int i = 0; i < 8; i++)
                #pragma unroll
                for (int j = 0; j < 8; j++) acc[i][j] = fmaf(a[i], b[j], acc[i][j]);
        }

        // ---- write output ----
        #pragma unroll
        for (int i = 0; i < 8; i++) {
            int nn = tile * TN + n0 + i;
            if (nn < NN) {
                float4 v0, v1;
                v0.x = acc[i][0]; v0.y = acc[i][1]; v0.z = acc[i][2]; v0.w = acc[i][3];
                v1.x = acc[i][4]; v1.y = acc[i][5]; v1.z = acc[i][6]; v1.w = acc[i][7];
                float4* op = reinterpret_cast<float4*>(out + (size_t)nn * D + c0);
                op[0] = v0; op[1] = v1;
            }
        }
    }
}

// ---------------------------------------------------------------------------
// Launch
// ---------------------------------------------------------------------------
extern "C" void kernel_launch(void* const* d_in, const int* in_sizes, int n_in,
                              void* d_out, int out_size) {
    const float* x    = (const float*)d_in[0];
    const void*  eidx = d_in[1];                 // int32 or int64 — detected on device
    // d_in[2] = batch (unused)
    const float* mw1 = (const float*)d_in[3];
    const float* mb1 = (const float*)d_in[4];
    const float* mw2 = (const float*)d_in[5];
    const float* mb2 = (const float*)d_in[6];
    const float* ow1 = (const float*)d_in[7];
    const float* ob1 = (const float*)d_in[8];
    const float* ow2 = (const float*)d_in[9];
    const float* ob2 = (const float*)d_in[10];
    float* out = (float*)d_out;

    cudaFuncSetAttribute(edge_kernel, cudaFuncAttributeMaxDynamicSharedMemorySize,
                         (int)sizeof(ESmem));
    cudaFuncSetAttribute(node_kernel, cudaFuncAttributeMaxDynamicSharedMemorySize,
                         (int)sizeof(NSmem));

    detect_kernel<<<1, 32>>>((const long long*)eidx);

    const int zero_elems = NN * D / 4;
    zero_agg_kernel<<<(zero_elems + 255) / 256, 256>>>();

    // 3 blocks/SM (~65.5 KB smem each) on 148 SMs
    edge_kernel<<<444, 128, sizeof(ESmem)>>>(x, eidx, mw1, mb1, mw2, mb2);

    // 1 block/SM (~113 KB smem), grid-stride over 782 node tiles
    node_kernel<<<148, 128, sizeof(NSmem)>>>(x, ow1, ob1, ow2, ob2, out);
}